// round 1
// baseline (speedup 1.0000x reference)
#include <cuda_runtime.h>

// Problem constants
#define BB   128
#define HHs  56          // spatial side
#define HWp  3136        // 56*56
#define EE   96
#define NHh  3
#define EHh  32
#define WSw  7
#define NWIN 64          // 8*8 windows
#define WWq  49          // 7*7 tokens per window

// Scratch (allocation-free rule: __device__ globals)
// layout: [b, H, win, qi, eh]  (contiguous per window-head)
__device__ float g_q[BB * NHh * NWIN * WWq * EHh];
__device__ float g_k[BB * NHh * NWIN * WWq * EHh];
__device__ float g_v[BB * NHh * NWIN * WWq * EHh];
// attention output back in [b, hw, E] layout (roll +3 applied)
__device__ float g_o[BB * HWp * EE];

// ---------------------------------------------------------------------------
// Kernel 1: qkv = x @ w1.T + b1, fused with cyclic shift (-4) and window
// partition scatter into g_q/g_k/g_v.
// Block: 288 threads (one per output column of the 3E=288 dim), TM=32 rows.
// ---------------------------------------------------------------------------
__global__ __launch_bounds__(288) void qkv_kernel(const float* __restrict__ x,
                                                  const float* __restrict__ w1,
                                                  const float* __restrict__ b1) {
    const int TM = 32;
    __shared__ float xs[TM][EE];   // 12 KB
    __shared__ int   basei[TM];

    int row0 = blockIdx.x * TM;
    int tid  = threadIdx.x;

    // load x tile (coalesced)
    for (int i = tid; i < TM * EE; i += 288) {
        int m = i / EE, e = i % EE;
        xs[m][e] = x[(row0 + m) * EE + e];
    }
    // per-row scatter base (shift -4, window partition)
    if (tid < TM) {
        int r  = row0 + tid;
        int b  = r / HWp;
        int p  = r % HWp;
        int h  = p / HHs, w = p % HHs;
        int hs = (h + HHs - 4) % HHs;      // h_s = (h-4) mod 56
        int ws = (w + HHs - 4) % HHs;
        int xw = hs / WSw, m1 = hs % WSw;
        int yw = ws / WSw, m2 = ws % WSw;
        basei[tid] = b * (NHh * NWIN * WWq * EHh)
                   + (xw * 8 + yw) * (WWq * EHh)
                   + (m1 * WSw + m2) * EHh;
    }
    __syncthreads();

    int c_out = tid;                       // 0..287 : column of qkv
    float bias = __ldg(b1 + c_out);
    float acc[TM];
#pragma unroll
    for (int m = 0; m < TM; m++) acc[m] = bias;

    const float* wrow = w1 + c_out * EE;
#pragma unroll 4
    for (int e = 0; e < EE; e++) {
        float wv = __ldg(wrow + e);
#pragma unroll
        for (int m = 0; m < TM; m++) acc[m] += xs[m][e] * wv;
    }

    // qkv col 288 splits as (c=E, k=3): c = col/3, ksel = col%3
    int c    = c_out / 3;
    int ksel = c_out % 3;
    int H    = c / EHh;
    int eh   = c % EHh;
    float* dst = (ksel == 0) ? g_q : (ksel == 1 ? g_k : g_v);
    int off = H * (NWIN * WWq * EHh) + eh;
#pragma unroll
    for (int m = 0; m < TM; m++) dst[basei[m] + off] = acc[m];
}

// ---------------------------------------------------------------------------
// Kernel 2: windowed attention. One block per (b, H, window). 256 threads.
// Scores + faithful shift masks + softmax + PV, output scattered with
// reverse window partition and roll(+3) into g_o [b,hw,E].
// ---------------------------------------------------------------------------
__global__ __launch_bounds__(256) void attn_kernel() {
    __shared__ float qs[WWq * 33];     // stride-33 padding: conflict-free
    __shared__ float ks[WWq * 33];
    __shared__ float vs[WWq * 33];
    __shared__ float S[WWq][52];

    int bw  = blockIdx.x;              // (b*3 + H)*64 + win
    int tid = threadIdx.x;
    int win = bw % NWIN;
    int xw  = win / 8, yw = win % 8;

    const float* qg = g_q + (size_t)bw * (WWq * EHh);
    const float* kg = g_k + (size_t)bw * (WWq * EHh);
    const float* vg = g_v + (size_t)bw * (WWq * EHh);

    for (int i = tid; i < WWq * EHh; i += 256) {
        int r = i / EHh, cix = i % EHh;
        qs[r * 33 + cix] = qg[i];
        ks[r * 33 + cix] = kg[i];
        vs[r * 33 + cix] = vg[i];
    }
    __syncthreads();

    bool mrow = (xw == 7);   // last window row: mask (m1>=4) boundary
    bool mcol = (yw == 7);   // last window col: mask (m2>=4) boundary

    for (int idx = tid; idx < WWq * WWq; idx += 256) {
        int qi = idx / WWq, ki = idx % WWq;
        float s = 0.f;
#pragma unroll
        for (int e = 0; e < EHh; e++) s += qs[qi * 33 + e] * ks[ki * 33 + e];
        s *= 0.17677669529663687f;     // 1/sqrt(32)
        if (mrow && ((qi / WSw >= 4) != (ki / WSw >= 4))) s = -1e30f;
        if (mcol && ((qi % WSw >= 4) != (ki % WSw >= 4))) s = -1e30f;
        S[qi][ki] = s;
    }
    __syncthreads();

    // softmax: one warp per row
    int wid = tid / 32, lane = tid % 32;
    for (int r = wid; r < WWq; r += 8) {
        float v1 = (lane < WWq)      ? S[r][lane]      : -1e30f;
        float v2 = (lane + 32 < WWq) ? S[r][lane + 32] : -1e30f;
        float mx = fmaxf(v1, v2);
#pragma unroll
        for (int o = 16; o; o >>= 1) mx = fmaxf(mx, __shfl_xor_sync(0xffffffffu, mx, o));
        float e1 = (lane < WWq)      ? __expf(v1 - mx) : 0.f;
        float e2 = (lane + 32 < WWq) ? __expf(v2 - mx) : 0.f;
        float sm = e1 + e2;
#pragma unroll
        for (int o = 16; o; o >>= 1) sm += __shfl_xor_sync(0xffffffffu, sm, o);
        float inv = __frcp_rn(sm);
        if (lane < WWq)      S[r][lane]      = e1 * inv;
        if (lane + 32 < WWq) S[r][lane + 32] = e2 * inv;
    }
    __syncthreads();

    int b = bw / (NHh * NWIN);
    int H = (bw / NWIN) % NHh;

    for (int idx = tid; idx < WWq * EHh; idx += 256) {
        int qi = idx / EHh, eh = idx % EHh;
        float acc = 0.f;
#pragma unroll
        for (int kk = 0; kk < WWq; kk++) acc += S[qi][kk] * vs[kk * 33 + eh];
        int m1 = qi / WSw, m2 = qi % WSw;
        int h = (xw * WSw + m1 + 3) % HHs;   // roll +3 (faithful)
        int w = (yw * WSw + m2 + 3) % HHs;
        g_o[((size_t)b * HWp + h * HHs + w) * EE + H * EHh + eh] = acc;
    }
}

// ---------------------------------------------------------------------------
// Kernel 3: out = g_o @ w2.T + b2.  192 threads: col = tid%96, row-half = tid/96.
// ---------------------------------------------------------------------------
__global__ __launch_bounds__(192) void proj_kernel(const float* __restrict__ w2,
                                                   const float* __restrict__ b2,
                                                   float* __restrict__ out) {
    const int TM = 32;
    __shared__ float os[TM][EE];   // 12 KB
    int row0 = blockIdx.x * TM;
    int tid  = threadIdx.x;

    for (int i = tid; i < TM * EE; i += 192) {
        int m = i / EE, e = i % EE;
        os[m][e] = g_o[(size_t)(row0 + m) * EE + e];
    }
    __syncthreads();

    int col = tid % EE;
    int s   = tid / EE;            // 0 or 1
    int m0  = s * 16;
    const float* wrow = w2 + col * EE;
    float bias = __ldg(b2 + col);
    float acc[16];
#pragma unroll
    for (int m = 0; m < 16; m++) acc[m] = bias;

#pragma unroll 4
    for (int e = 0; e < EE; e++) {
        float wv = __ldg(wrow + e);
#pragma unroll
        for (int m = 0; m < 16; m++) acc[m] += os[m0 + m][e] * wv;
    }
#pragma unroll
    for (int m = 0; m < 16; m++)
        out[(size_t)(row0 + m0 + m) * EE + col] = acc[m];
}

// ---------------------------------------------------------------------------
extern "C" void kernel_launch(void* const* d_in, const int* in_sizes, int n_in,
                              void* d_out, int out_size) {
    const float* x  = (const float*)d_in[0];
    const float* w1 = (const float*)d_in[1];
    const float* b1 = (const float*)d_in[2];
    const float* w2 = (const float*)d_in[3];
    const float* b2 = (const float*)d_in[4];
    float* out = (float*)d_out;

    qkv_kernel<<<(BB * HWp) / 32, 288>>>(x, w1, b1);
    attn_kernel<<<BB * NHh * NWIN, 256>>>();
    proj_kernel<<<(BB * HWp) / 32, 192>>>(w2, b2, out);
}

// round 3
// speedup vs baseline: 2.0631x; 2.0631x over previous
#include <cuda_runtime.h>

// Problem constants
#define BB   128
#define HHs  56          // spatial side
#define HWp  3136        // 56*56
#define EE   96
#define NHh  3
#define EHh  32
#define WSw  7
#define NWIN 64          // 8*8 windows
#define WWq  49          // 7*7 tokens per window

// Scratch (allocation-free rule: __device__ globals)
// layout: [b, H, win, qi, eh]  (contiguous per window-head)
__device__ float g_q[BB * NHh * NWIN * WWq * EHh];
__device__ float g_k[BB * NHh * NWIN * WWq * EHh];
__device__ float g_v[BB * NHh * NWIN * WWq * EHh];
// attention output back in [b, hw, E] layout (roll +3 applied)
__device__ float g_o[BB * HWp * EE];

// ---------------------------------------------------------------------------
// Kernel 1: qkv = x @ w1.T + b1, fused with cyclic shift (-4) and window
// partition scatter into g_q/g_k/g_v.
// Block tile 64 rows x 96 cols, 256 threads, 4x6 micro-tile per thread.
// Both smem operands stored K-major: A frag = 1 LDS.128, B frag = 3 LDS.64.
// ---------------------------------------------------------------------------
__global__ __launch_bounds__(256) void qkv_kernel(const float* __restrict__ x,
                                                  const float* __restrict__ w1,
                                                  const float* __restrict__ b1) {
    __shared__ float As[EE][64];    // [k][m]  24 KB
    __shared__ float Bs[EE][EE];    // [k][n]  36 KB
    __shared__ int   basei[64];

    const int row0  = blockIdx.x * 64;
    const int ncol0 = blockIdx.y * 96;
    const int tid   = threadIdx.x;

    // load x tile transposed into As[k][m]   (64 rows x 96 = 1536 float4)
    for (int i = tid; i < 1536; i += 256) {
        int m = i / 24, kc = i % 24;
        float4 vx = *(const float4*)(x + (size_t)(row0 + m) * EE + kc * 4);
        As[kc * 4 + 0][m] = vx.x;
        As[kc * 4 + 1][m] = vx.y;
        As[kc * 4 + 2][m] = vx.z;
        As[kc * 4 + 3][m] = vx.w;
    }
    // load w1 tile transposed into Bs[k][n]  (96 rows x 96 = 2304 float4)
    for (int i = tid; i < 2304; i += 256) {
        int n = i / 24, kc = i % 24;
        float4 wv = *(const float4*)(w1 + (size_t)(ncol0 + n) * EE + kc * 4);
        Bs[kc * 4 + 0][n] = wv.x;
        Bs[kc * 4 + 1][n] = wv.y;
        Bs[kc * 4 + 2][n] = wv.z;
        Bs[kc * 4 + 3][n] = wv.w;
    }
    // per-row scatter base (shift -4, window partition)
    if (tid < 64) {
        int r  = row0 + tid;
        int b  = r / HWp;
        int p  = r % HWp;
        int h  = p / HHs, w = p % HHs;
        int hs = (h + HHs - 4) % HHs;
        int ws = (w + HHs - 4) % HHs;
        int xw = hs / WSw, m1 = hs % WSw;
        int yw = ws / WSw, m2 = ws % WSw;
        basei[tid] = b * (NHh * NWIN * WWq * EHh)
                   + (xw * 8 + yw) * (WWq * EHh)
                   + (m1 * WSw + m2) * EHh;
    }
    __syncthreads();

    const int r  = tid / 16, c = tid % 16;
    const int m0 = r * 4, n0 = c * 6;

    float acc[4][6];
#pragma unroll
    for (int i = 0; i < 4; i++)
#pragma unroll
        for (int j = 0; j < 6; j++) acc[i][j] = 0.f;

#pragma unroll 4
    for (int k = 0; k < EE; k++) {
        float4 a  = *(const float4*)&As[k][m0];
        float2 b0 = *(const float2*)&Bs[k][n0];
        float2 b1v= *(const float2*)&Bs[k][n0 + 2];
        float2 b2 = *(const float2*)&Bs[k][n0 + 4];
        float av[4] = {a.x, a.y, a.z, a.w};
        float bv[6] = {b0.x, b0.y, b1v.x, b1v.y, b2.x, b2.y};
#pragma unroll
        for (int i = 0; i < 4; i++)
#pragma unroll
            for (int j = 0; j < 6; j++) acc[i][j] += av[i] * bv[j];
    }

    // epilogue: bias + scatter into g_q/g_k/g_v
#pragma unroll
    for (int j = 0; j < 6; j++) {
        int n    = ncol0 + n0 + j;
        float bv = __ldg(b1 + n);
        int cc   = n / 3;
        int ksel = n % 3;
        int H    = cc / EHh;
        int eh   = cc % EHh;
        float* dst = (ksel == 0) ? g_q : (ksel == 1 ? g_k : g_v);
        int off = H * (NWIN * WWq * EHh) + eh;
#pragma unroll
        for (int i = 0; i < 4; i++)
            dst[basei[m0 + i] + off] = acc[i][j] + bv;
    }
}

// ---------------------------------------------------------------------------
// Kernel 2: windowed attention. One block per (b, H, window). 256 threads.
// Q,K transposed to [e][qi] smem for vectorized score tiles (4x4 per thread).
// ---------------------------------------------------------------------------
__global__ __launch_bounds__(256) void attn_kernel() {
    __shared__ float Qt[EHh][64];       // [e][qi]  8 KB (qi padded to 64)
    __shared__ float Kt[EHh][64];       // [e][ki]  8 KB
    __shared__ float Vs[WWq * EHh];     // [kk][eh] row-major, 6.1 KB
    __shared__ float S[56][57];         // scores, padded

    const int bw  = blockIdx.x;          // ((b*3 + H)*64 + win)
    const int tid = threadIdx.x;
    const int win = bw % NWIN;
    const int xw  = win / 8, yw = win % 8;

    const float* qg = g_q + (size_t)bw * (WWq * EHh);
    const float* kg = g_k + (size_t)bw * (WWq * EHh);
    const float* vg = g_v + (size_t)bw * (WWq * EHh);

    // load + transpose q,k ; copy v   (49*32 = 1568 floats = 392 float4 each)
    for (int i = tid; i < 392; i += 256) {
        int qi = i >> 3, ec = i & 7;
        float4 qv = *(const float4*)(qg + qi * EHh + ec * 4);
        Qt[ec * 4 + 0][qi] = qv.x;
        Qt[ec * 4 + 1][qi] = qv.y;
        Qt[ec * 4 + 2][qi] = qv.z;
        Qt[ec * 4 + 3][qi] = qv.w;
        float4 kv = *(const float4*)(kg + qi * EHh + ec * 4);
        Kt[ec * 4 + 0][qi] = kv.x;
        Kt[ec * 4 + 1][qi] = kv.y;
        Kt[ec * 4 + 2][qi] = kv.z;
        Kt[ec * 4 + 3][qi] = kv.w;
        ((float4*)Vs)[i] = ((const float4*)vg)[i];
    }
    __syncthreads();

    const bool mrow = (xw == 7);
    const bool mcol = (yw == 7);

    // scores: 14x14 groups of 4x4 tiles (196 threads active), covers 56x56
    if (tid < 196) {
        int ti = tid % 14, tj = tid / 14;
        int q0 = ti * 4, k0 = tj * 4;
        float acc[4][4];
#pragma unroll
        for (int i = 0; i < 4; i++)
#pragma unroll
            for (int j = 0; j < 4; j++) acc[i][j] = 0.f;
#pragma unroll 8
        for (int e = 0; e < EHh; e++) {
            float4 qv = *(const float4*)&Qt[e][q0];
            float4 kv = *(const float4*)&Kt[e][k0];
            float qa[4] = {qv.x, qv.y, qv.z, qv.w};
            float ka[4] = {kv.x, kv.y, kv.z, kv.w};
#pragma unroll
            for (int i = 0; i < 4; i++)
#pragma unroll
                for (int j = 0; j < 4; j++) acc[i][j] += qa[i] * ka[j];
        }
#pragma unroll
        for (int i = 0; i < 4; i++) {
            int qi = q0 + i;
            bool qr = (qi / WSw >= 4);      // valid for qi<49; rows>=49 unused
            bool qc = (qi % WSw >= 4);
#pragma unroll
            for (int j = 0; j < 4; j++) {
                int ki = k0 + j;
                float s = acc[i][j] * 0.17677669529663687f;  // 1/sqrt(32)
                if (mrow && ((ki / WSw >= 4) != qr)) s = -1e30f;
                if (mcol && ((ki % WSw >= 4) != qc)) s = -1e30f;
                S[qi][ki] = s;
            }
        }
    }
    __syncthreads();

    // softmax: one warp per row (rows 0..48 only)
    {
        int wid = tid / 32, lane = tid % 32;
        for (int r = wid; r < WWq; r += 8) {
            float v1 = (lane < WWq)      ? S[r][lane]      : -1e30f;
            float v2 = (lane + 32 < WWq) ? S[r][lane + 32] : -1e30f;
            float mx = fmaxf(v1, v2);
#pragma unroll
            for (int o = 16; o; o >>= 1) mx = fmaxf(mx, __shfl_xor_sync(0xffffffffu, mx, o));
            float e1 = (lane < WWq)      ? __expf(v1 - mx) : 0.f;
            float e2 = (lane + 32 < WWq) ? __expf(v2 - mx) : 0.f;
            float sm = e1 + e2;
#pragma unroll
            for (int o = 16; o; o >>= 1) sm += __shfl_xor_sync(0xffffffffu, sm, o);
            float inv = __frcp_rn(sm);
            if (lane < WWq)      S[r][lane]      = e1 * inv;
            if (lane + 32 < WWq) S[r][lane + 32] = e2 * inv;
        }
    }
    __syncthreads();

    const int b = bw / (NHh * NWIN);
    const int H = (bw / NWIN) % NHh;

    // PV: 14 qi-groups x 8 eh-groups (112 threads), 4x4 micro-tile
    if (tid < 112) {
        int ti = tid % 14, tj = tid / 14;
        int q0 = ti * 4, e0 = tj * 4;
        float acc[4][4];
#pragma unroll
        for (int i = 0; i < 4; i++)
#pragma unroll
            for (int j = 0; j < 4; j++) acc[i][j] = 0.f;
#pragma unroll 7
        for (int kk = 0; kk < WWq; kk++) {
            float4 vv = *(const float4*)&Vs[kk * EHh + e0];
            float va[4] = {vv.x, vv.y, vv.z, vv.w};
            float pa[4];
#pragma unroll
            for (int i = 0; i < 4; i++) pa[i] = S[q0 + i][kk];
#pragma unroll
            for (int i = 0; i < 4; i++)
#pragma unroll
                for (int j = 0; j < 4; j++) acc[i][j] += pa[i] * va[j];
        }
#pragma unroll
        for (int i = 0; i < 4; i++) {
            int qi = q0 + i;
            if (qi < WWq) {
                int m1 = qi / WSw, m2 = qi % WSw;
                int h = (xw * WSw + m1 + 3) % HHs;   // roll +3 (faithful)
                int w = (yw * WSw + m2 + 3) % HHs;
                float* dst = g_o + ((size_t)b * HWp + h * HHs + w) * EE + H * EHh + e0;
#pragma unroll
                for (int j = 0; j < 4; j++) dst[j] = acc[i][j];
            }
        }
    }
}

// ---------------------------------------------------------------------------
// Kernel 3: out = g_o @ w2.T + b2. Same tiling as kernel 1 (64x96, 4x6).
// ---------------------------------------------------------------------------
__global__ __launch_bounds__(256) void proj_kernel(const float* __restrict__ w2,
                                                   const float* __restrict__ b2,
                                                   float* __restrict__ out) {
    __shared__ float As[EE][64];    // [k][m]
    __shared__ float Bs[EE][EE];    // [k][n]

    const int row0 = blockIdx.x * 64;
    const int tid  = threadIdx.x;

    for (int i = tid; i < 1536; i += 256) {
        int m = i / 24, kc = i % 24;
        float4 vx = *(const float4*)(g_o + (size_t)(row0 + m) * EE + kc * 4);
        As[kc * 4 + 0][m] = vx.x;
        As[kc * 4 + 1][m] = vx.y;
        As[kc * 4 + 2][m] = vx.z;
        As[kc * 4 + 3][m] = vx.w;
    }
    for (int i = tid; i < 2304; i += 256) {
        int n = i / 24, kc = i % 24;
        float4 wv = *(const float4*)(w2 + (size_t)n * EE + kc * 4);
        Bs[kc * 4 + 0][n] = wv.x;
        Bs[kc * 4 + 1][n] = wv.y;
        Bs[kc * 4 + 2][n] = wv.z;
        Bs[kc * 4 + 3][n] = wv.w;
    }
    __syncthreads();

    const int r  = tid / 16, c = tid % 16;
    const int m0 = r * 4, n0 = c * 6;

    float acc[4][6];
#pragma unroll
    for (int i = 0; i < 4; i++)
#pragma unroll
        for (int j = 0; j < 6; j++) acc[i][j] = 0.f;

#pragma unroll 4
    for (int k = 0; k < EE; k++) {
        float4 a  = *(const float4*)&As[k][m0];
        float2 b0 = *(const float2*)&Bs[k][n0];
        float2 b1v= *(const float2*)&Bs[k][n0 + 2];
        float2 b2v= *(const float2*)&Bs[k][n0 + 4];
        float av[4] = {a.x, a.y, a.z, a.w};
        float bv[6] = {b0.x, b0.y, b1v.x, b1v.y, b2v.x, b2v.y};
#pragma unroll
        for (int i = 0; i < 4; i++)
#pragma unroll
            for (int j = 0; j < 6; j++) acc[i][j] += av[i] * bv[j];
    }

#pragma unroll
    for (int j = 0; j < 6; j++) {
        float bv = __ldg(b2 + n0 + j);
#pragma unroll
        for (int i = 0; i < 4; i++)
            out[(size_t)(row0 + m0 + i) * EE + n0 + j] = acc[i][j] + bv;
    }
}

// ---------------------------------------------------------------------------
extern "C" void kernel_launch(void* const* d_in, const int* in_sizes, int n_in,
                              void* d_out, int out_size) {
    const float* x  = (const float*)d_in[0];
    const float* w1 = (const float*)d_in[1];
    const float* b1 = (const float*)d_in[2];
    const float* w2 = (const float*)d_in[3];
    const float* b2 = (const float*)d_in[4];
    float* out = (float*)d_out;

    dim3 g1(BB * HWp / 64, 3);
    qkv_kernel<<<g1, 256>>>(x, w1, b1);
    attn_kernel<<<BB * NHh * NWIN, 256>>>();
    proj_kernel<<<BB * HWp / 64, 256>>>(w2, b2, out);
}

// round 4
// speedup vs baseline: 2.7675x; 1.3414x over previous
#include <cuda_runtime.h>

// Problem constants
#define BB   128
#define HHs  56          // spatial side
#define HWp  3136        // 56*56
#define EE   96
#define NHh  3
#define EHh  32
#define WSw  7
#define NWIN 64          // 8*8 windows
#define WWq  49          // 7*7 tokens per window

typedef unsigned long long ull;

// duplicate a scalar float into both lanes of a packed f32x2
#define DUP2(d, s) asm("mov.b64 %0, {%1, %1};" : "=l"(d) : "r"(__float_as_uint(s)))
// packed fma: acc.lo += a.lo*b.lo ; acc.hi += a.hi*b.hi
#define FMA2(acc, a, b) asm("fma.rn.f32x2 %0, %1, %2, %0;" : "+l"(acc) : "l"(a), "l"(b))
// unpack packed f32x2 into two floats
#define UNPK(lo, hi, v) do { unsigned _ulo, _uhi; \
    asm("mov.b64 {%0, %1}, %2;" : "=r"(_ulo), "=r"(_uhi) : "l"(v)); \
    lo = __uint_as_float(_ulo); hi = __uint_as_float(_uhi); } while (0)

// Scratch (allocation-free rule: __device__ globals)
// layout: [b, H, win, qi, eh]  (contiguous per window-head)
__device__ float g_q[BB * NHh * NWIN * WWq * EHh];
__device__ float g_k[BB * NHh * NWIN * WWq * EHh];
__device__ float g_v[BB * NHh * NWIN * WWq * EHh];
// attention output back in [b, hw, E] layout (roll +3 applied)
__device__ float g_o[BB * HWp * EE];

// ---------------------------------------------------------------------------
// Kernel 1: qkv = x @ w1.T + b1, fused with cyclic shift (-4) and window
// partition scatter. Block tile 128 rows x 96 cols, 256 threads, 8x6
// micro-tile with f32x2 packed accumulation (packed over the m dimension).
// ---------------------------------------------------------------------------
__global__ __launch_bounds__(256) void qkv_kernel(const float* __restrict__ x,
                                                  const float* __restrict__ w1,
                                                  const float* __restrict__ b1) {
    __shared__ float As[EE][132];   // [k][m], padded (132 % 32 = 4) ~49.5 KB
    __shared__ float Bs[EE][100];   // [k][n], padded (100 % 32 = 4) ~37.5 KB
    __shared__ int   basei[128];

    const int row0  = blockIdx.x * 128;
    const int ncol0 = blockIdx.y * 96;
    const int tid   = threadIdx.x;

    // load x tile transposed into As[k][m]   (128 rows x 24 float4)
    for (int i = tid; i < 3072; i += 256) {
        int m = i / 24, kc = i % 24;
        float4 vx = *(const float4*)(x + (size_t)(row0 + m) * EE + kc * 4);
        As[kc * 4 + 0][m] = vx.x;
        As[kc * 4 + 1][m] = vx.y;
        As[kc * 4 + 2][m] = vx.z;
        As[kc * 4 + 3][m] = vx.w;
    }
    // load w1 tile transposed into Bs[k][n]  (96 rows x 24 float4)
    for (int i = tid; i < 2304; i += 256) {
        int n = i / 24, kc = i % 24;
        float4 wv = *(const float4*)(w1 + (size_t)(ncol0 + n) * EE + kc * 4);
        Bs[kc * 4 + 0][n] = wv.x;
        Bs[kc * 4 + 1][n] = wv.y;
        Bs[kc * 4 + 2][n] = wv.z;
        Bs[kc * 4 + 3][n] = wv.w;
    }
    // per-row scatter base (shift -4, window partition)
    if (tid < 128) {
        int r  = row0 + tid;
        int b  = r / HWp;
        int p  = r % HWp;
        int h  = p / HHs, w = p % HHs;
        int hs = (h + HHs - 4) % HHs;
        int ws = (w + HHs - 4) % HHs;
        int xw = hs / WSw, m1 = hs % WSw;
        int yw = ws / WSw, m2 = ws % WSw;
        basei[tid] = b * (NHh * NWIN * WWq * EHh)
                   + (xw * 8 + yw) * (WWq * EHh)
                   + (m1 * WSw + m2) * EHh;
    }
    __syncthreads();

    const int r  = tid / 16, c = tid % 16;
    const int m0 = r * 8, n0 = c * 6;

    ull acc[4][6];
#pragma unroll
    for (int i = 0; i < 4; i++)
#pragma unroll
        for (int j = 0; j < 6; j++) acc[i][j] = 0ULL;

#pragma unroll 4
    for (int k = 0; k < EE; k++) {
        ulonglong2 aA = *(const ulonglong2*)&As[k][m0];      // pairs (m0,m0+1),(m0+2,m0+3)
        ulonglong2 aB = *(const ulonglong2*)&As[k][m0 + 4];  // pairs (m0+4..7)
        ull ap[4] = {aA.x, aA.y, aB.x, aB.y};
#pragma unroll
        for (int j = 0; j < 6; j++) {
            ull bd;
            DUP2(bd, Bs[k][n0 + j]);
#pragma unroll
            for (int ip = 0; ip < 4; ip++) FMA2(acc[ip][j], ap[ip], bd);
        }
    }

    // epilogue: bias + scatter into g_q/g_k/g_v
#pragma unroll
    for (int j = 0; j < 6; j++) {
        int n    = ncol0 + n0 + j;
        float bv = __ldg(b1 + n);
        int cc   = n / 3;
        int ksel = n % 3;
        int H    = cc / EHh;
        int eh   = cc % EHh;
        float* dst = (ksel == 0) ? g_q : (ksel == 1 ? g_k : g_v);
        int off = H * (NWIN * WWq * EHh) + eh;
#pragma unroll
        for (int ip = 0; ip < 4; ip++) {
            float lo, hi;
            UNPK(lo, hi, acc[ip][j]);
            dst[basei[m0 + 2 * ip]     + off] = lo + bv;
            dst[basei[m0 + 2 * ip + 1] + off] = hi + bv;
        }
    }
}

// ---------------------------------------------------------------------------
// Kernel 2: windowed attention. One block per (b, H, window). 256 threads.
// f32x2-packed score (over ki) and PV (over eh) phases.
// ---------------------------------------------------------------------------
__global__ __launch_bounds__(256) void attn_kernel() {
    __shared__ float Qt[EHh][68];       // [e][qi], padded (68 % 32 = 4)
    __shared__ float Kt[EHh][68];       // [e][ki]
    __shared__ float Vs[WWq * EHh];     // [kk][eh] row-major
    __shared__ float S[56][57];         // scores, padded

    const int bw  = blockIdx.x;          // ((b*3 + H)*64 + win)
    const int tid = threadIdx.x;
    const int win = bw % NWIN;
    const int xw  = win / 8, yw = win % 8;

    const float* qg = g_q + (size_t)bw * (WWq * EHh);
    const float* kg = g_k + (size_t)bw * (WWq * EHh);
    const float* vg = g_v + (size_t)bw * (WWq * EHh);

    // load + transpose q,k ; copy v   (49*32 = 1568 floats = 392 float4 each)
    for (int i = tid; i < 392; i += 256) {
        int qi = i >> 3, ec = i & 7;
        float4 qv = *(const float4*)(qg + qi * EHh + ec * 4);
        Qt[ec * 4 + 0][qi] = qv.x;
        Qt[ec * 4 + 1][qi] = qv.y;
        Qt[ec * 4 + 2][qi] = qv.z;
        Qt[ec * 4 + 3][qi] = qv.w;
        float4 kv = *(const float4*)(kg + qi * EHh + ec * 4);
        Kt[ec * 4 + 0][qi] = kv.x;
        Kt[ec * 4 + 1][qi] = kv.y;
        Kt[ec * 4 + 2][qi] = kv.z;
        Kt[ec * 4 + 3][qi] = kv.w;
        ((float4*)Vs)[i] = ((const float4*)vg)[i];
    }
    __syncthreads();

    const bool mrow = (xw == 7);
    const bool mcol = (yw == 7);

    // scores: 14x14 groups of 4x4 tiles (196 threads), packed over ki pairs
    if (tid < 196) {
        int ti = tid % 14, tj = tid / 14;
        int q0 = ti * 4, k0 = tj * 4;
        ull acc[4][2];
#pragma unroll
        for (int i = 0; i < 4; i++) { acc[i][0] = 0ULL; acc[i][1] = 0ULL; }
#pragma unroll 4
        for (int e = 0; e < EHh; e++) {
            float4 qv = *(const float4*)&Qt[e][q0];
            ulonglong2 kp = *(const ulonglong2*)&Kt[e][k0];
            float qa[4] = {qv.x, qv.y, qv.z, qv.w};
#pragma unroll
            for (int i = 0; i < 4; i++) {
                ull qd;
                DUP2(qd, qa[i]);
                FMA2(acc[i][0], qd, kp.x);
                FMA2(acc[i][1], qd, kp.y);
            }
        }
#pragma unroll
        for (int i = 0; i < 4; i++) {
            int qi = q0 + i;
            bool qr = (qi / WSw >= 4);
            bool qc = (qi % WSw >= 4);
#pragma unroll
            for (int jp = 0; jp < 2; jp++) {
                float lo, hi;
                UNPK(lo, hi, acc[i][jp]);
                float sv[2] = {lo, hi};
#pragma unroll
                for (int d = 0; d < 2; d++) {
                    int ki = k0 + 2 * jp + d;
                    float s = sv[d] * 0.17677669529663687f;  // 1/sqrt(32)
                    if (mrow && ((ki / WSw >= 4) != qr)) s = -1e30f;
                    if (mcol && ((ki % WSw >= 4) != qc)) s = -1e30f;
                    S[qi][ki] = s;
                }
            }
        }
    }
    __syncthreads();

    // softmax: one warp per row (rows 0..48 only)
    {
        int wid = tid / 32, lane = tid % 32;
        for (int r = wid; r < WWq; r += 8) {
            float v1 = (lane < WWq)      ? S[r][lane]      : -1e30f;
            float v2 = (lane + 32 < WWq) ? S[r][lane + 32] : -1e30f;
            float mx = fmaxf(v1, v2);
#pragma unroll
            for (int o = 16; o; o >>= 1) mx = fmaxf(mx, __shfl_xor_sync(0xffffffffu, mx, o));
            float e1 = (lane < WWq)      ? __expf(v1 - mx) : 0.f;
            float e2 = (lane + 32 < WWq) ? __expf(v2 - mx) : 0.f;
            float sm = e1 + e2;
#pragma unroll
            for (int o = 16; o; o >>= 1) sm += __shfl_xor_sync(0xffffffffu, sm, o);
            float inv = __frcp_rn(sm);
            if (lane < WWq)      S[r][lane]      = e1 * inv;
            if (lane + 32 < WWq) S[r][lane + 32] = e2 * inv;
        }
    }
    __syncthreads();

    const int b = bw / (NHh * NWIN);
    const int H = (bw / NWIN) % NHh;

    // PV: 14 qi-groups x 8 eh-groups (112 threads), packed over eh pairs
    if (tid < 112) {
        int ti = tid % 14, tj = tid / 14;
        int q0 = ti * 4, e0 = tj * 4;
        ull acc[4][2];
#pragma unroll
        for (int i = 0; i < 4; i++) { acc[i][0] = 0ULL; acc[i][1] = 0ULL; }
#pragma unroll 7
        for (int kk = 0; kk < WWq; kk++) {
            ulonglong2 vp = *(const ulonglong2*)&Vs[kk * EHh + e0];
#pragma unroll
            for (int i = 0; i < 4; i++) {
                ull pd;
                DUP2(pd, S[q0 + i][kk]);
                FMA2(acc[i][0], pd, vp.x);
                FMA2(acc[i][1], pd, vp.y);
            }
        }
#pragma unroll
        for (int i = 0; i < 4; i++) {
            int qi = q0 + i;
            if (qi < WWq) {
                int m1 = qi / WSw, m2 = qi % WSw;
                int h = (xw * WSw + m1 + 3) % HHs;   // roll +3 (faithful)
                int w = (yw * WSw + m2 + 3) % HHs;
                float* dst = g_o + ((size_t)b * HWp + h * HHs + w) * EE + H * EHh + e0;
                float l0, h0, l1, h1;
                UNPK(l0, h0, acc[i][0]);
                UNPK(l1, h1, acc[i][1]);
                *(float4*)dst = make_float4(l0, h0, l1, h1);
            }
        }
    }
}

// ---------------------------------------------------------------------------
// Kernel 3: out = g_o @ w2.T + b2. Same 128x96 / 8x6 packed tiling.
// ---------------------------------------------------------------------------
__global__ __launch_bounds__(256) void proj_kernel(const float* __restrict__ w2,
                                                   const float* __restrict__ b2,
                                                   float* __restrict__ out) {
    __shared__ float As[EE][132];
    __shared__ float Bs[EE][100];

    const int row0 = blockIdx.x * 128;
    const int tid  = threadIdx.x;

    for (int i = tid; i < 3072; i += 256) {
        int m = i / 24, kc = i % 24;
        float4 vx = *(const float4*)(g_o + (size_t)(row0 + m) * EE + kc * 4);
        As[kc * 4 + 0][m] = vx.x;
        As[kc * 4 + 1][m] = vx.y;
        As[kc * 4 + 2][m] = vx.z;
        As[kc * 4 + 3][m] = vx.w;
    }
    for (int i = tid; i < 2304; i += 256) {
        int n = i / 24, kc = i % 24;
        float4 wv = *(const float4*)(w2 + (size_t)n * EE + kc * 4);
        Bs[kc * 4 + 0][n] = wv.x;
        Bs[kc * 4 + 1][n] = wv.y;
        Bs[kc * 4 + 2][n] = wv.z;
        Bs[kc * 4 + 3][n] = wv.w;
    }
    __syncthreads();

    const int r  = tid / 16, c = tid % 16;
    const int m0 = r * 8, n0 = c * 6;

    ull acc[4][6];
#pragma unroll
    for (int i = 0; i < 4; i++)
#pragma unroll
        for (int j = 0; j < 6; j++) acc[i][j] = 0ULL;

#pragma unroll 4
    for (int k = 0; k < EE; k++) {
        ulonglong2 aA = *(const ulonglong2*)&As[k][m0];
        ulonglong2 aB = *(const ulonglong2*)&As[k][m0 + 4];
        ull ap[4] = {aA.x, aA.y, aB.x, aB.y};
#pragma unroll
        for (int j = 0; j < 6; j++) {
            ull bd;
            DUP2(bd, Bs[k][n0 + j]);
#pragma unroll
            for (int ip = 0; ip < 4; ip++) FMA2(acc[ip][j], ap[ip], bd);
        }
    }

#pragma unroll
    for (int j = 0; j < 6; j++) {
        float bv = __ldg(b2 + n0 + j);
#pragma unroll
        for (int ip = 0; ip < 4; ip++) {
            float lo, hi;
            UNPK(lo, hi, acc[ip][j]);
            out[(size_t)(row0 + m0 + 2 * ip)     * EE + n0 + j] = lo + bv;
            out[(size_t)(row0 + m0 + 2 * ip + 1) * EE + n0 + j] = hi + bv;
        }
    }
}

// ---------------------------------------------------------------------------
extern "C" void kernel_launch(void* const* d_in, const int* in_sizes, int n_in,
                              void* d_out, int out_size) {
    const float* x  = (const float*)d_in[0];
    const float* w1 = (const float*)d_in[1];
    const float* b1 = (const float*)d_in[2];
    const float* w2 = (const float*)d_in[3];
    const float* b2 = (const float*)d_in[4];
    float* out = (float*)d_out;

    dim3 g1(BB * HWp / 128, 3);
    qkv_kernel<<<g1, 256>>>(x, w1, b1);
    attn_kernel<<<BB * NHh * NWIN, 256>>>();
    proj_kernel<<<BB * HWp / 128, 256>>>(w2, b2, out);
}

// round 6
// speedup vs baseline: 2.8685x; 1.0365x over previous
#include <cuda_runtime.h>
#include <cuda_bf16.h>
#include <cstdint>

// Problem constants
#define BB   128
#define HHs  56
#define HWp  3136
#define EE   96
#define NHh  3
#define EHh  32
#define WSw  7
#define NWIN 64
#define WWq  49

typedef unsigned long long ull;
typedef uint32_t u32;

// ---------------- f32x2 helpers (attention kernel) ----------------
#define DUP2(d, s) asm("mov.b64 %0, {%1, %1};" : "=l"(d) : "r"(__float_as_uint(s)))
#define FMA2(acc, a, b) asm("fma.rn.f32x2 %0, %1, %2, %0;" : "+l"(acc) : "l"(a), "l"(b))
#define UNPK(lo, hi, v) do { unsigned _ulo, _uhi; \
    asm("mov.b64 {%0, %1}, %2;" : "=r"(_ulo), "=r"(_uhi) : "l"(v)); \
    lo = __uint_as_float(_ulo); hi = __uint_as_float(_uhi); } while (0)

// ---------------- mma.sync / ldmatrix helpers (sm_80+, no 'a' needed) ----------------
__device__ __forceinline__ u32 smem_u32(const void* p) {
    u32 a;
    asm("{ .reg .u64 t; cvta.to.shared.u64 t, %1; cvt.u32.u64 %0, t; }" : "=r"(a) : "l"(p));
    return a;
}
#define LDSM4(r, addr) \
    asm volatile("ldmatrix.sync.aligned.m8n8.x4.shared.b16 {%0,%1,%2,%3}, [%4];" \
        : "=r"((r)[0]), "=r"((r)[1]), "=r"((r)[2]), "=r"((r)[3]) : "r"(addr))
#define MMA_BF16(d, a, b0, b1) \
    asm volatile("mma.sync.aligned.m16n8k16.row.col.f32.bf16.bf16.f32 " \
        "{%0,%1,%2,%3}, {%4,%5,%6,%7}, {%8,%9}, {%0,%1,%2,%3};" \
        : "+f"((d)[0]), "+f"((d)[1]), "+f"((d)[2]), "+f"((d)[3]) \
        : "r"((a)[0]), "r"((a)[1]), "r"((a)[2]), "r"((a)[3]), "r"(b0), "r"(b1))

// ---------------- scratch (allocation-free rule) ----------------
__device__ float g_q[BB * NHh * NWIN * WWq * EHh];
__device__ float g_k[BB * NHh * NWIN * WWq * EHh];
__device__ float g_v[BB * NHh * NWIN * WWq * EHh];
__device__ float g_o[BB * HWp * EE];
// bf16 hi/lo weights, row-major [n][k], packed 2 halves per u32
__device__ __align__(16) u32 g_w1h[288 * 48];
__device__ __align__(16) u32 g_w1l[288 * 48];
__device__ __align__(16) u32 g_w2h[96 * 48];
__device__ __align__(16) u32 g_w2l[96 * 48];

// split fp32 pair -> bf16-hi pair, bf16-lo (residual) pair
__device__ __forceinline__ void cvt_pair(float a, float b, u32& hp, u32& lp) {
    __nv_bfloat16 h0 = __float2bfloat16(a), h1 = __float2bfloat16(b);
    float f0 = __bfloat162float(h0), f1 = __bfloat162float(h1);
    __nv_bfloat16 l0 = __float2bfloat16(a - f0), l1 = __float2bfloat16(b - f1);
    hp = (u32)__bfloat16_as_ushort(h0) | ((u32)__bfloat16_as_ushort(h1) << 16);
    lp = (u32)__bfloat16_as_ushort(l0) | ((u32)__bfloat16_as_ushort(l1) << 16);
}

__global__ __launch_bounds__(256) void wconv_kernel(const float* __restrict__ w1,
                                                    const float* __restrict__ w2) {
    int tid0 = blockIdx.x * 256 + threadIdx.x;
    int stride = gridDim.x * 256;
    for (int p = tid0; p < 288 * 48; p += stride) {
        int n = p / 48, kp = (p % 48) * 2;
        float2 v = *(const float2*)(w1 + (size_t)n * 96 + kp);
        u32 hp, lp; cvt_pair(v.x, v.y, hp, lp);
        g_w1h[p] = hp; g_w1l[p] = lp;
    }
    for (int p = tid0; p < 96 * 48; p += stride) {
        int n = p / 48, kp = (p % 48) * 2;
        float2 v = *(const float2*)(w2 + (size_t)n * 96 + kp);
        u32 hp, lp; cvt_pair(v.x, v.y, hp, lp);
        g_w2h[p] = hp; g_w2l[p] = lp;
    }
}

// ---------------- smem layout ----------------
// A tiles: 128 rows x 104 halves (208B stride) hi+lo; B: 96 rows x 104 halves hi+lo.
// C stage (after mma): 128 rows x 104 floats, overlaps A region.
#define SA_STRIDE 208
#define SM_AH   0
#define SM_AL   26624
#define SM_BH   53248
#define SM_BL   73216
#define SM_BIAS 93184
#define SM_BASE 93568
#define SM_CST  0
#define SM_SZ   94080

// ---------------------------------------------------------------------------
// Shared mainloop: 8 warps, warp strip M=16, N=96 (12 n-chunks), K=96.
// 3-term bf16 error compensation. Results staged to smem [row][104] f32.
// ---------------------------------------------------------------------------
__device__ __forceinline__ void mma_mainloop_and_stage(unsigned char* sm, u32 sbase,
                                                       int tid) {
    const int wid = tid >> 5, lane = tid & 31;
    const int m0 = wid * 16;

    // ldmatrix lane address components
    const u32 a_row = (u32)(m0 + (lane & 7) + ((lane >> 3) & 1) * 8);
    const u32 a_k   = (u32)((lane >> 4) * 8);
    const u32 aaddrH = sbase + SM_AH + a_row * SA_STRIDE + a_k * 2;
    const u32 aaddrL = sbase + SM_AL + a_row * SA_STRIDE + a_k * 2;
    const u32 b_row = (u32)((lane & 7) + ((lane >= 16) ? 8 : 0));
    const u32 b_k   = (u32)(((lane >> 3) & 1) * 8);
    const u32 baddrH = sbase + SM_BH + b_row * SA_STRIDE + b_k * 2;
    const u32 baddrL = sbase + SM_BL + b_row * SA_STRIDE + b_k * 2;

    float d[12][4];
#pragma unroll
    for (int i = 0; i < 12; i++)
#pragma unroll
        for (int j = 0; j < 4; j++) d[i][j] = 0.f;

#pragma unroll
    for (int k0 = 0; k0 < 96; k0 += 16) {
        u32 ah[4], al[4];
        LDSM4(ah, aaddrH + k0 * 2);
        LDSM4(al, aaddrL + k0 * 2);
#pragma unroll
        for (int np = 0; np < 6; np++) {
            u32 bh[4], bl[4];
            LDSM4(bh, baddrH + (u32)np * 16 * SA_STRIDE + k0 * 2);
            LDSM4(bl, baddrL + (u32)np * 16 * SA_STRIDE + k0 * 2);
            MMA_BF16(d[2 * np],     ah, bh[0], bh[1]);
            MMA_BF16(d[2 * np + 1], ah, bh[2], bh[3]);
            MMA_BF16(d[2 * np],     ah, bl[0], bl[1]);
            MMA_BF16(d[2 * np + 1], ah, bl[2], bl[3]);
            MMA_BF16(d[2 * np],     al, bh[0], bh[1]);
            MMA_BF16(d[2 * np + 1], al, bh[2], bh[3]);
        }
    }
    __syncthreads();   // all operand reads done before C overwrites A region

    const int crow = m0 + lane / 4;
    const int ccol = 2 * (lane & 3);
#pragma unroll
    for (int nc = 0; nc < 12; nc++) {
        int col = nc * 8 + ccol;
        *(float2*)(sm + SM_CST + ((size_t)crow * 104 + col) * 4)       = make_float2(d[nc][0], d[nc][1]);
        *(float2*)(sm + SM_CST + ((size_t)(crow + 8) * 104 + col) * 4) = make_float2(d[nc][2], d[nc][3]);
    }
    __syncthreads();
}

// load fp32 A rows -> bf16 hi/lo smem (padded row-major)
__device__ __forceinline__ void load_A_tile(unsigned char* sm, const float* __restrict__ src,
                                            int row0, int tid) {
    for (int i = tid; i < 3072; i += 256) {
        int row = i / 24, k = (i % 24) * 4;
        float4 v = *(const float4*)(src + (size_t)(row0 + row) * EE + k);
        u32 hp0, lp0, hp1, lp1;
        cvt_pair(v.x, v.y, hp0, lp0);
        cvt_pair(v.z, v.w, hp1, lp1);
        u32 off = (u32)row * SA_STRIDE + (u32)k * 2;
        *(uint2*)(sm + SM_AH + off) = make_uint2(hp0, hp1);
        *(uint2*)(sm + SM_AL + off) = make_uint2(lp0, lp1);
    }
}
// copy pre-converted bf16 weights -> padded smem (96 rows x 12 float4)
__device__ __forceinline__ void load_B_tile(unsigned char* sm, const u32* wh, const u32* wl,
                                            int tid) {
    for (int i = tid; i < 1152; i += 256) {
        int row = i / 12, c4 = i % 12;
        *(float4*)(sm + SM_BH + (u32)row * SA_STRIDE + c4 * 16) = ((const float4*)(wh + (size_t)row * 48))[c4];
        *(float4*)(sm + SM_BL + (u32)row * SA_STRIDE + c4 * 16) = ((const float4*)(wl + (size_t)row * 48))[c4];
    }
}

// ---------------------------------------------------------------------------
// Kernel 1: qkv slab GEMM (tensor cores). grid=(3136,3). Epilogue scatters
// with cyclic shift (-4) + window partition into g_q/g_k/g_v.
// ---------------------------------------------------------------------------
__global__ __launch_bounds__(256) void qkv_mma(const float* __restrict__ x,
                                               const float* __restrict__ b1) {
    extern __shared__ unsigned char sm[];
    const u32 sbase = smem_u32(sm);
    const int tid = threadIdx.x;
    const int row0 = blockIdx.x * 128;
    const int nb   = blockIdx.y;

    if (tid < 96) *(float*)(sm + SM_BIAS + tid * 4) = b1[nb * 96 + tid];
    if (tid < 128) {
        int r  = row0 + tid;
        int b  = r / HWp;
        int p  = r % HWp;
        int h  = p / HHs, w = p % HHs;
        int hs = (h + HHs - 4) % HHs;     // cyclic shift -4 (faithful)
        int ws = (w + HHs - 4) % HHs;
        int xw = hs / WSw, m1 = hs % WSw;
        int yw = ws / WSw, m2 = ws % WSw;
        *(int*)(sm + SM_BASE + tid * 4) =
            b * (NHh * NWIN * WWq * EHh) + (xw * 8 + yw) * (WWq * EHh) + (m1 * WSw + m2) * EHh;
    }
    load_B_tile(sm, g_w1h + nb * 96 * 48, g_w1l + nb * 96 * 48, tid);
    load_A_tile(sm, x, row0, tid);
    __syncthreads();

    mma_mainloop_and_stage(sm, sbase, tid);

    // epilogue: bias + scatter (slab nb == head H)
    if (tid < 128) {
        const float* crow = (const float*)(sm + SM_CST + (size_t)tid * 416);
        const float* bias = (const float*)(sm + SM_BIAS);
        int bi = *(const int*)(sm + SM_BASE + tid * 4) + nb * (NWIN * WWq * EHh);
#pragma unroll
        for (int ksel = 0; ksel < 3; ksel++) {
            float* dst = (ksel == 0 ? g_q : (ksel == 1 ? g_k : g_v)) + bi;
#pragma unroll
            for (int e0 = 0; e0 < 32; e0 += 4) {
                float4 o;
                o.x = crow[3 * e0 + ksel]       + bias[3 * e0 + ksel];
                o.y = crow[3 * (e0 + 1) + ksel] + bias[3 * (e0 + 1) + ksel];
                o.z = crow[3 * (e0 + 2) + ksel] + bias[3 * (e0 + 2) + ksel];
                o.w = crow[3 * (e0 + 3) + ksel] + bias[3 * (e0 + 3) + ksel];
                *(float4*)(dst + e0) = o;
            }
        }
    }
}

// ---------------------------------------------------------------------------
// Kernel 3: proj GEMM (tensor cores). grid=3136. out = g_o @ w2.T + b2.
// ---------------------------------------------------------------------------
__global__ __launch_bounds__(256) void proj_mma(const float* __restrict__ b2,
                                                float* __restrict__ out) {
    extern __shared__ unsigned char sm[];
    const u32 sbase = smem_u32(sm);
    const int tid = threadIdx.x;
    const int row0 = blockIdx.x * 128;

    if (tid < 96) *(float*)(sm + SM_BIAS + tid * 4) = b2[tid];
    load_B_tile(sm, g_w2h, g_w2l, tid);
    load_A_tile(sm, g_o, row0, tid);
    __syncthreads();

    mma_mainloop_and_stage(sm, sbase, tid);

    if (tid < 128) {
        const float* crow = (const float*)(sm + SM_CST + (size_t)tid * 416);
        const float* bias = (const float*)(sm + SM_BIAS);
        float* dst = out + (size_t)(row0 + tid) * EE;
#pragma unroll
        for (int c0 = 0; c0 < 96; c0 += 4)
            *(float4*)(dst + c0) = make_float4(crow[c0] + bias[c0], crow[c0 + 1] + bias[c0 + 1],
                                               crow[c0 + 2] + bias[c0 + 2], crow[c0 + 3] + bias[c0 + 3]);
    }
}

// ---------------------------------------------------------------------------
// Kernel 2: windowed attention (unchanged from R4 passing kernel).
// ---------------------------------------------------------------------------
__global__ __launch_bounds__(256) void attn_kernel() {
    __shared__ float Qt[EHh][68];
    __shared__ float Kt[EHh][68];
    __shared__ float Vs[WWq * EHh];
    __shared__ float S[56][57];

    const int bw  = blockIdx.x;
    const int tid = threadIdx.x;
    const int win = bw % NWIN;
    const int xw  = win / 8, yw = win % 8;

    const float* qg = g_q + (size_t)bw * (WWq * EHh);
    const float* kg = g_k + (size_t)bw * (WWq * EHh);
    const float* vg = g_v + (size_t)bw * (WWq * EHh);

    for (int i = tid; i < 392; i += 256) {
        int qi = i >> 3, ec = i & 7;
        float4 qv = *(const float4*)(qg + qi * EHh + ec * 4);
        Qt[ec * 4 + 0][qi] = qv.x;
        Qt[ec * 4 + 1][qi] = qv.y;
        Qt[ec * 4 + 2][qi] = qv.z;
        Qt[ec * 4 + 3][qi] = qv.w;
        float4 kv = *(const float4*)(kg + qi * EHh + ec * 4);
        Kt[ec * 4 + 0][qi] = kv.x;
        Kt[ec * 4 + 1][qi] = kv.y;
        Kt[ec * 4 + 2][qi] = kv.z;
        Kt[ec * 4 + 3][qi] = kv.w;
        ((float4*)Vs)[i] = ((const float4*)vg)[i];
    }
    __syncthreads();

    const bool mrow = (xw == 7);
    const bool mcol = (yw == 7);

    if (tid < 196) {
        int ti = tid % 14, tj = tid / 14;
        int q0 = ti * 4, k0 = tj * 4;
        ull acc[4][2];
#pragma unroll
        for (int i = 0; i < 4; i++) { acc[i][0] = 0ULL; acc[i][1] = 0ULL; }
#pragma unroll 4
        for (int e = 0; e < EHh; e++) {
            float4 qv = *(const float4*)&Qt[e][q0];
            ulonglong2 kp = *(const ulonglong2*)&Kt[e][k0];
            float qa[4] = {qv.x, qv.y, qv.z, qv.w};
#pragma unroll
            for (int i = 0; i < 4; i++) {
                ull qd;
                DUP2(qd, qa[i]);
                FMA2(acc[i][0], qd, kp.x);
                FMA2(acc[i][1], qd, kp.y);
            }
        }
#pragma unroll
        for (int i = 0; i < 4; i++) {
            int qi = q0 + i;
            bool qr = (qi / WSw >= 4);
            bool qc = (qi % WSw >= 4);
#pragma unroll
            for (int jp = 0; jp < 2; jp++) {
                float lo, hi;
                UNPK(lo, hi, acc[i][jp]);
                float sv[2] = {lo, hi};
#pragma unroll
                for (int d = 0; d < 2; d++) {
                    int ki = k0 + 2 * jp + d;
                    float s = sv[d] * 0.17677669529663687f;
                    if (mrow && ((ki / WSw >= 4) != qr)) s = -1e30f;
                    if (mcol && ((ki % WSw >= 4) != qc)) s = -1e30f;
                    S[qi][ki] = s;
                }
            }
        }
    }
    __syncthreads();

    {
        int wid = tid / 32, lane = tid % 32;
        for (int r = wid; r < WWq; r += 8) {
            float v1 = (lane < WWq)      ? S[r][lane]      : -1e30f;
            float v2 = (lane + 32 < WWq) ? S[r][lane + 32] : -1e30f;
            float mx = fmaxf(v1, v2);
#pragma unroll
            for (int o = 16; o; o >>= 1) mx = fmaxf(mx, __shfl_xor_sync(0xffffffffu, mx, o));
            float e1 = (lane < WWq)      ? __expf(v1 - mx) : 0.f;
            float e2 = (lane + 32 < WWq) ? __expf(v2 - mx) : 0.f;
            float sm = e1 + e2;
#pragma unroll
            for (int o = 16; o; o >>= 1) sm += __shfl_xor_sync(0xffffffffu, sm, o);
            float inv = __frcp_rn(sm);
            if (lane < WWq)      S[r][lane]      = e1 * inv;
            if (lane + 32 < WWq) S[r][lane + 32] = e2 * inv;
        }
    }
    __syncthreads();

    const int b = bw / (NHh * NWIN);
    const int H = (bw / NWIN) % NHh;

    if (tid < 112) {
        int ti = tid % 14, tj = tid / 14;
        int q0 = ti * 4, e0 = tj * 4;
        ull acc[4][2];
#pragma unroll
        for (int i = 0; i < 4; i++) { acc[i][0] = 0ULL; acc[i][1] = 0ULL; }
#pragma unroll 7
        for (int kk = 0; kk < WWq; kk++) {
            ulonglong2 vp = *(const ulonglong2*)&Vs[kk * EHh + e0];
#pragma unroll
            for (int i = 0; i < 4; i++) {
                ull pd;
                DUP2(pd, S[q0 + i][kk]);
                FMA2(acc[i][0], pd, vp.x);
                FMA2(acc[i][1], pd, vp.y);
            }
        }
#pragma unroll
        for (int i = 0; i < 4; i++) {
            int qi = q0 + i;
            if (qi < WWq) {
                int m1 = qi / WSw, m2 = qi % WSw;
                int h = (xw * WSw + m1 + 3) % HHs;
                int w = (yw * WSw + m2 + 3) % HHs;
                float* dst = g_o + ((size_t)b * HWp + h * HHs + w) * EE + H * EHh + e0;
                float l0, h0, l1, h1;
                UNPK(l0, h0, acc[i][0]);
                UNPK(l1, h1, acc[i][1]);
                *(float4*)dst = make_float4(l0, h0, l1, h1);
            }
        }
    }
}

// ---------------------------------------------------------------------------
extern "C" void kernel_launch(void* const* d_in, const int* in_sizes, int n_in,
                              void* d_out, int out_size) {
    const float* x  = (const float*)d_in[0];
    const float* w1 = (const float*)d_in[1];
    const float* b1 = (const float*)d_in[2];
    const float* w2 = (const float*)d_in[3];
    const float* b2 = (const float*)d_in[4];
    float* out = (float*)d_out;

    cudaFuncSetAttribute(qkv_mma, cudaFuncAttributeMaxDynamicSharedMemorySize, SM_SZ);
    cudaFuncSetAttribute(proj_mma, cudaFuncAttributeMaxDynamicSharedMemorySize, SM_SZ);

    wconv_kernel<<<64, 256>>>(w1, w2);
    qkv_mma<<<dim3(BB * HWp / 128, 3), 256, SM_SZ>>>(x, b1);
    attn_kernel<<<BB * NHh * NWIN, 256>>>();
    proj_mma<<<BB * HWp / 128, 256, SM_SZ>>>(b2, out);
}

// round 8
// speedup vs baseline: 2.9223x; 1.0188x over previous
#include <cuda_runtime.h>
#include <cuda_bf16.h>
#include <cstdint>

// Problem constants
#define BB   128
#define HHs  56
#define HWp  3136
#define EE   96
#define NHh  3
#define EHh  32
#define WSw  7
#define NWIN 64
#define WWq  49

typedef unsigned long long ull;
typedef uint32_t u32;

// ---------------- f32x2 helpers (attention kernel) ----------------
#define DUP2(d, s) asm("mov.b64 %0, {%1, %1};" : "=l"(d) : "r"(__float_as_uint(s)))
#define FMA2(acc, a, b) asm("fma.rn.f32x2 %0, %1, %2, %0;" : "+l"(acc) : "l"(a), "l"(b))
#define UNPK(lo, hi, v) do { unsigned _ulo, _uhi; \
    asm("mov.b64 {%0, %1}, %2;" : "=r"(_ulo), "=r"(_uhi) : "l"(v)); \
    lo = __uint_as_float(_ulo); hi = __uint_as_float(_uhi); } while (0)

// ---------------- mma.sync / ldmatrix helpers (sm_80+, no 'a' needed) ----------------
__device__ __forceinline__ u32 smem_u32(const void* p) {
    u32 a;
    asm("{ .reg .u64 t; cvta.to.shared.u64 t, %1; cvt.u32.u64 %0, t; }" : "=r"(a) : "l"(p));
    return a;
}
#define LDSM4(r, addr) \
    asm volatile("ldmatrix.sync.aligned.m8n8.x4.shared.b16 {%0,%1,%2,%3}, [%4];" \
        : "=r"((r)[0]), "=r"((r)[1]), "=r"((r)[2]), "=r"((r)[3]) : "r"(addr))
#define MMA_BF16(d, a, b0, b1) \
    asm volatile("mma.sync.aligned.m16n8k16.row.col.f32.bf16.bf16.f32 " \
        "{%0,%1,%2,%3}, {%4,%5,%6,%7}, {%8,%9}, {%0,%1,%2,%3};" \
        : "+f"((d)[0]), "+f"((d)[1]), "+f"((d)[2]), "+f"((d)[3]) \
        : "r"((a)[0]), "r"((a)[1]), "r"((a)[2]), "r"((a)[3]), "r"(b0), "r"(b1))

// ---------------- scratch (allocation-free rule) ----------------
__device__ float g_q[BB * NHh * NWIN * WWq * EHh];
__device__ float g_k[BB * NHh * NWIN * WWq * EHh];
__device__ float g_v[BB * NHh * NWIN * WWq * EHh];
__device__ float g_o[BB * HWp * EE];
// bf16 hi/lo weights, row-major [n][k], packed 2 halves per u32
__device__ __align__(16) u32 g_w1h[288 * 48];
__device__ __align__(16) u32 g_w1l[288 * 48];
__device__ __align__(16) u32 g_w2h[96 * 48];
__device__ __align__(16) u32 g_w2l[96 * 48];

// split fp32 pair -> bf16-hi pair, bf16-lo (residual) pair
__device__ __forceinline__ void cvt_pair(float a, float b, u32& hp, u32& lp) {
    __nv_bfloat16 h0 = __float2bfloat16(a), h1 = __float2bfloat16(b);
    float f0 = __bfloat162float(h0), f1 = __bfloat162float(h1);
    __nv_bfloat16 l0 = __float2bfloat16(a - f0), l1 = __float2bfloat16(b - f1);
    hp = (u32)__bfloat16_as_ushort(h0) | ((u32)__bfloat16_as_ushort(h1) << 16);
    lp = (u32)__bfloat16_as_ushort(l0) | ((u32)__bfloat16_as_ushort(l1) << 16);
}

__global__ __launch_bounds__(256) void wconv_kernel(const float* __restrict__ w1,
                                                    const float* __restrict__ w2) {
    int tid0 = blockIdx.x * 256 + threadIdx.x;
    int stride = gridDim.x * 256;
    for (int p = tid0; p < 288 * 48; p += stride) {
        int n = p / 48, kp = (p % 48) * 2;
        float2 v = *(const float2*)(w1 + (size_t)n * 96 + kp);
        u32 hp, lp; cvt_pair(v.x, v.y, hp, lp);
        g_w1h[p] = hp; g_w1l[p] = lp;
    }
    for (int p = tid0; p < 96 * 48; p += stride) {
        int n = p / 48, kp = (p % 48) * 2;
        float2 v = *(const float2*)(w2 + (size_t)n * 96 + kp);
        u32 hp, lp; cvt_pair(v.x, v.y, hp, lp);
        g_w2h[p] = hp; g_w2l[p] = lp;
    }
}

// ---------------- smem layout (GEMM kernels) ----------------
#define SA_STRIDE 208
#define SM_AH   0                 // 128 x 208B = 26624
#define SM_AL   26624             // -> 53248
#define SM_BH   53248             // 96 x 208B = 19968 -> 73216
#define SM_BL   73216             // -> 93184
#define SM_BIAS 93184             // 288 floats -> 94336
#define SM_BASE 94336             // 128 ints  -> 94848
#define SM_SZ   94848

// load fp32 A rows -> bf16 hi/lo smem (padded row-major)
__device__ __forceinline__ void load_A_tile(unsigned char* sm, const float* __restrict__ src,
                                            int row0, int tid) {
    for (int i = tid; i < 3072; i += 256) {
        int row = i / 24, k = (i % 24) * 4;
        float4 v = *(const float4*)(src + (size_t)(row0 + row) * EE + k);
        u32 hp0, lp0, hp1, lp1;
        cvt_pair(v.x, v.y, hp0, lp0);
        cvt_pair(v.z, v.w, hp1, lp1);
        u32 off = (u32)row * SA_STRIDE + (u32)k * 2;
        *(uint2*)(sm + SM_AH + off) = make_uint2(hp0, hp1);
        *(uint2*)(sm + SM_AL + off) = make_uint2(lp0, lp1);
    }
}
// copy pre-converted bf16 weights -> padded smem (96 rows x 12 float4)
__device__ __forceinline__ void load_B_tile(unsigned char* sm, const u32* wh, const u32* wl,
                                            int tid) {
    for (int i = tid; i < 1152; i += 256) {
        int row = i / 12, c4 = i % 12;
        *(float4*)(sm + SM_BH + (u32)row * SA_STRIDE + c4 * 16) = ((const float4*)(wh + (size_t)row * 48))[c4];
        *(float4*)(sm + SM_BL + (u32)row * SA_STRIDE + c4 * 16) = ((const float4*)(wl + (size_t)row * 48))[c4];
    }
}

// 3-term bf16 compensated mainloop: fills d[12][4] for a 16x96 warp strip
__device__ __forceinline__ void mma_slab(u32 aaddrH, u32 aaddrL, u32 baddrH, u32 baddrL,
                                         float d[12][4]) {
#pragma unroll
    for (int i = 0; i < 12; i++)
#pragma unroll
        for (int j = 0; j < 4; j++) d[i][j] = 0.f;
#pragma unroll
    for (int k0 = 0; k0 < 96; k0 += 16) {
        u32 ah[4], al[4];
        LDSM4(ah, aaddrH + k0 * 2);
        LDSM4(al, aaddrL + k0 * 2);
#pragma unroll
        for (int np = 0; np < 6; np++) {
            u32 bh[4], bl[4];
            LDSM4(bh, baddrH + (u32)np * 16 * SA_STRIDE + k0 * 2);
            LDSM4(bl, baddrL + (u32)np * 16 * SA_STRIDE + k0 * 2);
            MMA_BF16(d[2 * np],     ah, bh[0], bh[1]);
            MMA_BF16(d[2 * np + 1], ah, bh[2], bh[3]);
            MMA_BF16(d[2 * np],     ah, bl[0], bl[1]);
            MMA_BF16(d[2 * np + 1], ah, bl[2], bl[3]);
            MMA_BF16(d[2 * np],     al, bh[0], bh[1]);
            MMA_BF16(d[2 * np + 1], al, bh[2], bh[3]);
        }
    }
}

// ---------------------------------------------------------------------------
// Kernel 1: qkv GEMM, ALL 3 slabs per CTA (A converted once). grid=3136.
// Direct-fragment epilogue: bias + shift/window scatter into g_q/g_k/g_v.
// ---------------------------------------------------------------------------
__global__ __launch_bounds__(256) void qkv_mma(const float* __restrict__ x,
                                               const float* __restrict__ b1) {
    extern __shared__ unsigned char sm[];
    const u32 sbase = smem_u32(sm);
    const int tid = threadIdx.x, wid = tid >> 5, lane = tid & 31;
    const int row0 = blockIdx.x * 128;

    for (int i = tid; i < 288; i += 256) *(float*)(sm + SM_BIAS + i * 4) = b1[i];
    if (tid < 128) {
        int r  = row0 + tid;
        int b  = r / HWp;
        int p  = r % HWp;
        int h  = p / HHs, w = p % HHs;
        int hs = (h + HHs - 4) % HHs;     // cyclic shift -4 (faithful)
        int ws = (w + HHs - 4) % HHs;
        int xw = hs / WSw, m1 = hs % WSw;
        int yw = ws / WSw, m2 = ws % WSw;
        *(int*)(sm + SM_BASE + tid * 4) =
            b * (NHh * NWIN * WWq * EHh) + (xw * 8 + yw) * (WWq * EHh) + (m1 * WSw + m2) * EHh;
    }
    load_A_tile(sm, x, row0, tid);

    const int m0 = wid * 16;
    const u32 a_row = (u32)(m0 + (lane & 7) + ((lane >> 3) & 1) * 8);
    const u32 a_k   = (u32)((lane >> 4) * 8);
    const u32 aaddrH = sbase + SM_AH + a_row * SA_STRIDE + a_k * 2;
    const u32 aaddrL = sbase + SM_AL + a_row * SA_STRIDE + a_k * 2;
    const u32 b_row = (u32)((lane & 7) + ((lane >= 16) ? 8 : 0));
    const u32 b_k   = (u32)(((lane >> 3) & 1) * 8);
    const u32 baddrH = sbase + SM_BH + b_row * SA_STRIDE + b_k * 2;
    const u32 baddrL = sbase + SM_BL + b_row * SA_STRIDE + b_k * 2;
    const int crow0 = m0 + lane / 4;
    const int ccol  = 2 * (lane & 3);

#pragma unroll
    for (int nb = 0; nb < 3; nb++) {
        __syncthreads();   // B buffer free (prev slab's LDSMs done); nb=0: A/B fills done
        load_B_tile(sm, g_w1h + (size_t)nb * 96 * 48, g_w1l + (size_t)nb * 96 * 48, tid);
        __syncthreads();

        float d[12][4];
        mma_slab(aaddrH, aaddrL, baddrH, baddrL, d);

        // direct epilogue: d[nc][0,1] -> row crow0 cols n,n+1 ; d[nc][2,3] -> row crow0+8
        const int boff = nb * (NWIN * WWq * EHh);
        const int bi0 = *(const int*)(sm + SM_BASE + crow0 * 4) + boff;
        const int bi1 = *(const int*)(sm + SM_BASE + (crow0 + 8) * 4) + boff;
#pragma unroll
        for (int nc = 0; nc < 12; nc++) {
            int n = nc * 8 + ccol;
            float2 bv = *(const float2*)(sm + SM_BIAS + (nb * 96 + n) * 4);
            {
                int eh = n / 3, ks = n % 3;
                float* base = (ks == 0) ? g_q : (ks == 1 ? g_k : g_v);
                base[bi0 + eh] = d[nc][0] + bv.x;
                base[bi1 + eh] = d[nc][2] + bv.x;
            }
            {
                int n1 = n + 1;
                int eh = n1 / 3, ks = n1 % 3;
                float* base = (ks == 0) ? g_q : (ks == 1 ? g_k : g_v);
                base[bi0 + eh] = d[nc][1] + bv.y;
                base[bi1 + eh] = d[nc][3] + bv.y;
            }
        }
    }
}

// ---------------------------------------------------------------------------
// Kernel 3: proj GEMM. grid=3136. out = g_o @ w2.T + b2, direct epilogue.
// ---------------------------------------------------------------------------
__global__ __launch_bounds__(256) void proj_mma(const float* __restrict__ b2,
                                                float* __restrict__ out) {
    extern __shared__ unsigned char sm[];
    const u32 sbase = smem_u32(sm);
    const int tid = threadIdx.x, wid = tid >> 5, lane = tid & 31;
    const int row0 = blockIdx.x * 128;

    for (int i = tid; i < 96; i += 256) *(float*)(sm + SM_BIAS + i * 4) = b2[i];
    load_B_tile(sm, g_w2h, g_w2l, tid);
    load_A_tile(sm, g_o, row0, tid);
    __syncthreads();

    const int m0 = wid * 16;
    const u32 a_row = (u32)(m0 + (lane & 7) + ((lane >> 3) & 1) * 8);
    const u32 a_k   = (u32)((lane >> 4) * 8);
    const u32 aaddrH = sbase + SM_AH + a_row * SA_STRIDE + a_k * 2;
    const u32 aaddrL = sbase + SM_AL + a_row * SA_STRIDE + a_k * 2;
    const u32 b_row = (u32)((lane & 7) + ((lane >= 16) ? 8 : 0));
    const u32 b_k   = (u32)(((lane >> 3) & 1) * 8);
    const u32 baddrH = sbase + SM_BH + b_row * SA_STRIDE + b_k * 2;
    const u32 baddrL = sbase + SM_BL + b_row * SA_STRIDE + b_k * 2;

    float d[12][4];
    mma_slab(aaddrH, aaddrL, baddrH, baddrL, d);

    const int crow0 = m0 + lane / 4;
    const int ccol  = 2 * (lane & 3);
    float* dst0 = out + (size_t)(row0 + crow0) * EE;
    float* dst1 = out + (size_t)(row0 + crow0 + 8) * EE;
#pragma unroll
    for (int nc = 0; nc < 12; nc++) {
        int n = nc * 8 + ccol;
        float2 bv = *(const float2*)(sm + SM_BIAS + n * 4);
        *(float2*)(dst0 + n) = make_float2(d[nc][0] + bv.x, d[nc][1] + bv.y);
        *(float2*)(dst1 + n) = make_float2(d[nc][2] + bv.x, d[nc][3] + bv.y);
    }
}

// ---------------------------------------------------------------------------
// Kernel 2: windowed attention (R4 structure; PV phase rebalanced to 200 thr).
// ---------------------------------------------------------------------------
__global__ __launch_bounds__(256) void attn_kernel() {
    __shared__ float Qt[EHh][68];
    __shared__ float Kt[EHh][68];
    __shared__ float Vs[WWq * EHh];
    __shared__ float S[56][57];

    const int bw  = blockIdx.x;
    const int tid = threadIdx.x;
    const int win = bw % NWIN;
    const int xw  = win / 8, yw = win % 8;

    const float* qg = g_q + (size_t)bw * (WWq * EHh);
    const float* kg = g_k + (size_t)bw * (WWq * EHh);
    const float* vg = g_v + (size_t)bw * (WWq * EHh);

    for (int i = tid; i < 392; i += 256) {
        int qi = i >> 3, ec = i & 7;
        float4 qv = *(const float4*)(qg + qi * EHh + ec * 4);
        Qt[ec * 4 + 0][qi] = qv.x;
        Qt[ec * 4 + 1][qi] = qv.y;
        Qt[ec * 4 + 2][qi] = qv.z;
        Qt[ec * 4 + 3][qi] = qv.w;
        float4 kv = *(const float4*)(kg + qi * EHh + ec * 4);
        Kt[ec * 4 + 0][qi] = kv.x;
        Kt[ec * 4 + 1][qi] = kv.y;
        Kt[ec * 4 + 2][qi] = kv.z;
        Kt[ec * 4 + 3][qi] = kv.w;
        ((float4*)Vs)[i] = ((const float4*)vg)[i];
    }
    __syncthreads();

    const bool mrow = (xw == 7);
    const bool mcol = (yw == 7);

    if (tid < 196) {
        int ti = tid % 14, tj = tid / 14;
        int q0 = ti * 4, k0 = tj * 4;
        ull acc[4][2];
#pragma unroll
        for (int i = 0; i < 4; i++) { acc[i][0] = 0ULL; acc[i][1] = 0ULL; }
#pragma unroll 4
        for (int e = 0; e < EHh; e++) {
            float4 qv = *(const float4*)&Qt[e][q0];
            ulonglong2 kp = *(const ulonglong2*)&Kt[e][k0];
            float qa[4] = {qv.x, qv.y, qv.z, qv.w};
#pragma unroll
            for (int i = 0; i < 4; i++) {
                ull qd;
                DUP2(qd, qa[i]);
                FMA2(acc[i][0], qd, kp.x);
                FMA2(acc[i][1], qd, kp.y);
            }
        }
#pragma unroll
        for (int i = 0; i < 4; i++) {
            int qi = q0 + i;
            bool qr = (qi / WSw >= 4);
            bool qc = (qi % WSw >= 4);
#pragma unroll
            for (int jp = 0; jp < 2; jp++) {
                float lo, hi;
                UNPK(lo, hi, acc[i][jp]);
                float sv[2] = {lo, hi};
#pragma unroll
                for (int d = 0; d < 2; d++) {
                    int ki = k0 + 2 * jp + d;
                    float s = sv[d] * 0.17677669529663687f;
                    if (mrow && ((ki / WSw >= 4) != qr)) s = -1e30f;
                    if (mcol && ((ki % WSw >= 4) != qc)) s = -1e30f;
                    S[qi][ki] = s;
                }
            }
        }
    }
    __syncthreads();

    {
        int wid = tid / 32, lane = tid % 32;
        for (int r = wid; r < WWq; r += 8) {
            float v1 = (lane < WWq)      ? S[r][lane]      : -1e30f;
            float v2 = (lane + 32 < WWq) ? S[r][lane + 32] : -1e30f;
            float mx = fmaxf(v1, v2);
#pragma unroll
            for (int o = 16; o; o >>= 1) mx = fmaxf(mx, __shfl_xor_sync(0xffffffffu, mx, o));
            float e1 = (lane < WWq)      ? __expf(v1 - mx) : 0.f;
            float e2 = (lane + 32 < WWq) ? __expf(v2 - mx) : 0.f;
            float sm = e1 + e2;
#pragma unroll
            for (int o = 16; o; o >>= 1) sm += __shfl_xor_sync(0xffffffffu, sm, o);
            float inv = __frcp_rn(sm);
            if (lane < WWq)      S[r][lane]      = e1 * inv;
            if (lane + 32 < WWq) S[r][lane + 32] = e2 * inv;
        }
    }
    __syncthreads();

    const int b = bw / (NHh * NWIN);
    const int H = (bw / NWIN) % NHh;

    // PV: 25 qi-groups (of 2) x 8 eh-groups (of 4) = 200 threads, 2x4 micro
    if (tid < 200) {
        int ti = tid % 25, tj = tid / 25;
        int q0 = ti * 2, e0 = tj * 4;
        ull acc[2][2];
        acc[0][0] = acc[0][1] = acc[1][0] = acc[1][1] = 0ULL;
#pragma unroll 7
        for (int kk = 0; kk < WWq; kk++) {
            ulonglong2 vp = *(const ulonglong2*)&Vs[kk * EHh + e0];
            ull pd0, pd1;
            DUP2(pd0, S[q0][kk]);
            DUP2(pd1, S[q0 + 1][kk]);
            FMA2(acc[0][0], pd0, vp.x);
            FMA2(acc[0][1], pd0, vp.y);
            FMA2(acc[1][0], pd1, vp.x);
            FMA2(acc[1][1], pd1, vp.y);
        }
#pragma unroll
        for (int i = 0; i < 2; i++) {
            int qi = q0 + i;
            if (qi < WWq) {
                int m1 = qi / WSw, m2 = qi % WSw;
                int h = (xw * WSw + m1 + 3) % HHs;   // roll +3 (faithful)
                int w = (yw * WSw + m2 + 3) % HHs;
                float* dst = g_o + ((size_t)b * HWp + h * HHs + w) * EE + H * EHh + e0;
                float l0, h0, l1, h1;
                UNPK(l0, h0, acc[i][0]);
                UNPK(l1, h1, acc[i][1]);
                *(float4*)dst = make_float4(l0, h0, l1, h1);
            }
        }
    }
}

// ---------------------------------------------------------------------------
extern "C" void kernel_launch(void* const* d_in, const int* in_sizes, int n_in,
                              void* d_out, int out_size) {
    const float* x  = (const float*)d_in[0];
    const float* w1 = (const float*)d_in[1];
    const float* b1 = (const float*)d_in[2];
    const float* w2 = (const float*)d_in[3];
    const float* b2 = (const float*)d_in[4];
    float* out = (float*)d_out;

    cudaFuncSetAttribute(qkv_mma, cudaFuncAttributeMaxDynamicSharedMemorySize, SM_SZ);
    cudaFuncSetAttribute(proj_mma, cudaFuncAttributeMaxDynamicSharedMemorySize, SM_SZ);

    wconv_kernel<<<64, 256>>>(w1, w2);
    qkv_mma<<<BB * HWp / 128, 256, SM_SZ>>>(x, b1);
    attn_kernel<<<BB * NHh * NWIN, 256>>>();
    proj_mma<<<BB * HWp / 128, 256, SM_SZ>>>(b2, out);
}

// round 10
// speedup vs baseline: 3.3580x; 1.1491x over previous
#include <cuda_runtime.h>
#include <cuda_bf16.h>
#include <cstdint>

// Problem constants
#define BB   128
#define HHs  56
#define HWp  3136
#define EE   96
#define NHh  3
#define EHh  32
#define WSw  7
#define NWIN 64
#define WWq  49

typedef unsigned long long ull;
typedef uint32_t u32;

// ---------------- f32x2 helpers (attention kernel) ----------------
#define DUP2(d, s) asm("mov.b64 %0, {%1, %1};" : "=l"(d) : "r"(__float_as_uint(s)))
#define FMA2(acc, a, b) asm("fma.rn.f32x2 %0, %1, %2, %0;" : "+l"(acc) : "l"(a), "l"(b))
#define UNPK(lo, hi, v) do { unsigned _ulo, _uhi; \
    asm("mov.b64 {%0, %1}, %2;" : "=r"(_ulo), "=r"(_uhi) : "l"(v)); \
    lo = __uint_as_float(_ulo); hi = __uint_as_float(_uhi); } while (0)

// ---------------- mma.sync / ldmatrix helpers (sm_80+) ----------------
__device__ __forceinline__ u32 smem_u32(const void* p) {
    u32 a;
    asm("{ .reg .u64 t; cvta.to.shared.u64 t, %1; cvt.u32.u64 %0, t; }" : "=r"(a) : "l"(p));
    return a;
}
#define LDSM4(r, addr) \
    asm volatile("ldmatrix.sync.aligned.m8n8.x4.shared.b16 {%0,%1,%2,%3}, [%4];" \
        : "=r"((r)[0]), "=r"((r)[1]), "=r"((r)[2]), "=r"((r)[3]) : "r"(addr))
#define MMA_BF16(d, a, b0, b1) \
    asm volatile("mma.sync.aligned.m16n8k16.row.col.f32.bf16.bf16.f32 " \
        "{%0,%1,%2,%3}, {%4,%5,%6,%7}, {%8,%9}, {%0,%1,%2,%3};" \
        : "+f"((d)[0]), "+f"((d)[1]), "+f"((d)[2]), "+f"((d)[3]) \
        : "r"((a)[0]), "r"((a)[1]), "r"((a)[2]), "r"((a)[3]), "r"(b0), "r"(b1))

// ---------------- scratch (allocation-free rule) ----------------
__device__ float g_qkv[(size_t)BB * HWp * 288];   // identity layout [row][288]
__device__ float g_o[(size_t)BB * HWp * EE];
// bf16 hi/lo weights, row-major [n][k], packed 2 halves per u32
__device__ __align__(16) u32 g_w1h[288 * 48];
__device__ __align__(16) u32 g_w1l[288 * 48];
__device__ __align__(16) u32 g_w2h[96 * 48];
__device__ __align__(16) u32 g_w2l[96 * 48];

// split fp32 pair -> bf16-hi pair, bf16-lo (residual) pair
__device__ __forceinline__ void cvt_pair(float a, float b, u32& hp, u32& lp) {
    __nv_bfloat16 h0 = __float2bfloat16(a), h1 = __float2bfloat16(b);
    float f0 = __bfloat162float(h0), f1 = __bfloat162float(h1);
    __nv_bfloat16 l0 = __float2bfloat16(a - f0), l1 = __float2bfloat16(b - f1);
    hp = (u32)__bfloat16_as_ushort(h0) | ((u32)__bfloat16_as_ushort(h1) << 16);
    lp = (u32)__bfloat16_as_ushort(l0) | ((u32)__bfloat16_as_ushort(l1) << 16);
}

__global__ __launch_bounds__(256) void wconv_kernel(const float* __restrict__ w1,
                                                    const float* __restrict__ w2) {
    int tid0 = blockIdx.x * 256 + threadIdx.x;
    int stride = gridDim.x * 256;
    for (int p = tid0; p < 288 * 48; p += stride) {
        int n = p / 48, kp = (p % 48) * 2;
        float2 v = *(const float2*)(w1 + (size_t)n * 96 + kp);
        u32 hp, lp; cvt_pair(v.x, v.y, hp, lp);
        g_w1h[p] = hp; g_w1l[p] = lp;
    }
    for (int p = tid0; p < 96 * 48; p += stride) {
        int n = p / 48, kp = (p % 48) * 2;
        float2 v = *(const float2*)(w2 + (size_t)n * 96 + kp);
        u32 hp, lp; cvt_pair(v.x, v.y, hp, lp);
        g_w2h[p] = hp; g_w2l[p] = lp;
    }
}

// ---------------- smem layout (GEMM kernels) ----------------
#define SA_STRIDE 208
#define SM_AH   0                 // 128 x 208B = 26624
#define SM_AL   26624             // -> 53248
#define SM_BH   53248             // 96 x 208B = 19968 -> 73216
#define SM_BL   73216             // -> 93184
#define SM_BIAS 93184             // 288 floats -> 94336
#define SM_SZ   94336

// load fp32 A rows -> bf16 hi/lo smem (padded row-major)
__device__ __forceinline__ void load_A_tile(unsigned char* sm, const float* __restrict__ src,
                                            int row0, int tid) {
    for (int i = tid; i < 3072; i += 256) {
        int row = i / 24, k = (i % 24) * 4;
        float4 v = *(const float4*)(src + (size_t)(row0 + row) * EE + k);
        u32 hp0, lp0, hp1, lp1;
        cvt_pair(v.x, v.y, hp0, lp0);
        cvt_pair(v.z, v.w, hp1, lp1);
        u32 off = (u32)row * SA_STRIDE + (u32)k * 2;
        *(uint2*)(sm + SM_AH + off) = make_uint2(hp0, hp1);
        *(uint2*)(sm + SM_AL + off) = make_uint2(lp0, lp1);
    }
}
// copy pre-converted bf16 weights -> padded smem (96 rows x 12 float4)
__device__ __forceinline__ void load_B_tile(unsigned char* sm, const u32* wh, const u32* wl,
                                            int tid) {
    for (int i = tid; i < 1152; i += 256) {
        int row = i / 12, c4 = i % 12;
        *(float4*)(sm + SM_BH + (u32)row * SA_STRIDE + c4 * 16) = ((const float4*)(wh + (size_t)row * 48))[c4];
        *(float4*)(sm + SM_BL + (u32)row * SA_STRIDE + c4 * 16) = ((const float4*)(wl + (size_t)row * 48))[c4];
    }
}

// 3-term bf16 compensated mainloop: fills d[12][4] for a 16x96 warp strip
__device__ __forceinline__ void mma_slab(u32 aaddrH, u32 aaddrL, u32 baddrH, u32 baddrL,
                                         float d[12][4]) {
#pragma unroll
    for (int i = 0; i < 12; i++)
#pragma unroll
        for (int j = 0; j < 4; j++) d[i][j] = 0.f;
#pragma unroll
    for (int k0 = 0; k0 < 96; k0 += 16) {
        u32 ah[4], al[4];
        LDSM4(ah, aaddrH + k0 * 2);
        LDSM4(al, aaddrL + k0 * 2);
#pragma unroll
        for (int np = 0; np < 6; np++) {
            u32 bh[4], bl[4];
            LDSM4(bh, baddrH + (u32)np * 16 * SA_STRIDE + k0 * 2);
            LDSM4(bl, baddrL + (u32)np * 16 * SA_STRIDE + k0 * 2);
            MMA_BF16(d[2 * np],     ah, bh[0], bh[1]);
            MMA_BF16(d[2 * np + 1], ah, bh[2], bh[3]);
            MMA_BF16(d[2 * np],     ah, bl[0], bl[1]);
            MMA_BF16(d[2 * np + 1], ah, bl[2], bl[3]);
            MMA_BF16(d[2 * np],     al, bh[0], bh[1]);
            MMA_BF16(d[2 * np + 1], al, bh[2], bh[3]);
        }
    }
}

// ---------------------------------------------------------------------------
// Kernel 1: qkv GEMM, 3 slabs per CTA, A converted once. grid=3136.
// Epilogue: COALESCED float2 into identity-layout g_qkv (no scatter).
// ---------------------------------------------------------------------------
__global__ __launch_bounds__(256) void qkv_mma(const float* __restrict__ x,
                                               const float* __restrict__ b1) {
    extern __shared__ unsigned char sm[];
    const u32 sbase = smem_u32(sm);
    const int tid = threadIdx.x, wid = tid >> 5, lane = tid & 31;
    const int row0 = blockIdx.x * 128;

    for (int i = tid; i < 288; i += 256) *(float*)(sm + SM_BIAS + i * 4) = b1[i];
    load_A_tile(sm, x, row0, tid);

    const int m0 = wid * 16;
    const u32 a_row = (u32)(m0 + (lane & 7) + ((lane >> 3) & 1) * 8);
    const u32 a_k   = (u32)((lane >> 4) * 8);
    const u32 aaddrH = sbase + SM_AH + a_row * SA_STRIDE + a_k * 2;
    const u32 aaddrL = sbase + SM_AL + a_row * SA_STRIDE + a_k * 2;
    const u32 b_row = (u32)((lane & 7) + ((lane >= 16) ? 8 : 0));
    const u32 b_k   = (u32)(((lane >> 3) & 1) * 8);
    const u32 baddrH = sbase + SM_BH + b_row * SA_STRIDE + b_k * 2;
    const u32 baddrL = sbase + SM_BL + b_row * SA_STRIDE + b_k * 2;
    const int crow0 = m0 + lane / 4;
    const int ccol  = 2 * (lane & 3);

#pragma unroll
    for (int nb = 0; nb < 3; nb++) {
        __syncthreads();   // prev slab's LDSMs done (nb=0: A/bias fills done)
        load_B_tile(sm, g_w1h + (size_t)nb * 4608, g_w1l + (size_t)nb * 4608, tid);
        __syncthreads();

        float d[12][4];
        mma_slab(aaddrH, aaddrL, baddrH, baddrL, d);

        float* dst0 = g_qkv + (size_t)(row0 + crow0) * 288 + nb * 96;
        float* dst1 = g_qkv + (size_t)(row0 + crow0 + 8) * 288 + nb * 96;
#pragma unroll
        for (int nc = 0; nc < 12; nc++) {
            int n = nc * 8 + ccol;
            float2 bv = *(const float2*)(sm + SM_BIAS + (nb * 96 + n) * 4);
            *(float2*)(dst0 + n) = make_float2(d[nc][0] + bv.x, d[nc][1] + bv.y);
            *(float2*)(dst1 + n) = make_float2(d[nc][2] + bv.x, d[nc][3] + bv.y);
        }
    }
}

// ---------------------------------------------------------------------------
// Kernel 3: proj GEMM. grid=3136. out = g_o @ w2.T + b2, direct epilogue.
// ---------------------------------------------------------------------------
__global__ __launch_bounds__(256) void proj_mma(const float* __restrict__ b2,
                                                float* __restrict__ out) {
    extern __shared__ unsigned char sm[];
    const u32 sbase = smem_u32(sm);
    const int tid = threadIdx.x, wid = tid >> 5, lane = tid & 31;
    const int row0 = blockIdx.x * 128;

    for (int i = tid; i < 96; i += 256) *(float*)(sm + SM_BIAS + i * 4) = b2[i];
    load_B_tile(sm, g_w2h, g_w2l, tid);
    load_A_tile(sm, g_o, row0, tid);
    __syncthreads();

    const int m0 = wid * 16;
    const u32 a_row = (u32)(m0 + (lane & 7) + ((lane >> 3) & 1) * 8);
    const u32 a_k   = (u32)((lane >> 4) * 8);
    const u32 aaddrH = sbase + SM_AH + a_row * SA_STRIDE + a_k * 2;
    const u32 aaddrL = sbase + SM_AL + a_row * SA_STRIDE + a_k * 2;
    const u32 b_row = (u32)((lane & 7) + ((lane >= 16) ? 8 : 0));
    const u32 b_k   = (u32)(((lane >> 3) & 1) * 8);
    const u32 baddrH = sbase + SM_BH + b_row * SA_STRIDE + b_k * 2;
    const u32 baddrL = sbase + SM_BL + b_row * SA_STRIDE + b_k * 2;

    float d[12][4];
    mma_slab(aaddrH, aaddrL, baddrH, baddrL, d);

    const int crow0 = m0 + lane / 4;
    const int ccol  = 2 * (lane & 3);
    float* dst0 = out + (size_t)(row0 + crow0) * EE;
    float* dst1 = out + (size_t)(row0 + crow0 + 8) * EE;
#pragma unroll
    for (int nc = 0; nc < 12; nc++) {
        int n = nc * 8 + ccol;
        float2 bv = *(const float2*)(sm + SM_BIAS + n * 4);
        *(float2*)(dst0 + n) = make_float2(d[nc][0] + bv.x, d[nc][1] + bv.y);
        *(float2*)(dst1 + n) = make_float2(d[nc][2] + bv.x, d[nc][3] + bv.y);
    }
}

// ---------------------------------------------------------------------------
// Kernel 2: windowed attention. Gathers head-H 384B runs from identity-layout
// g_qkv (shift -4 applied via gather index), de-interleaves into smem.
// Shrunk smem (31.2KB) -> 7 CTAs/SM. 13x13 score tiling into S[52][52].
// ---------------------------------------------------------------------------
__global__ __launch_bounds__(256) void attn_kernel() {
    __shared__ float Qt[EHh][52];       // [e][qi]
    __shared__ float Kt[EHh][52];       // [e][ki]
    __shared__ float Vs[WWq * 36];      // [kk][eh] padded to 36
    __shared__ float S[52][52];

    const int bw  = blockIdx.x;          // ((b*3 + H)*64 + win)
    const int tid = threadIdx.x;
    const int win = bw % NWIN;
    const int xw  = win / 8, yw = win % 8;
    const int b   = bw / (NHh * NWIN);
    const int H   = (bw / NWIN) % NHh;

    // gather + de-interleave: 49 tokens x 24 float4 (cols 96H..96H+95)
    for (int i = tid; i < WWq * 24; i += 256) {
        int qi = i / 24, j = i % 24;
        int m1 = qi / WSw, m2 = qi - m1 * WSw;
        int h = xw * WSw + m1 + 4; if (h >= HHs) h -= HHs;   // inverse shift (-4 roll)
        int w = yw * WSw + m2 + 4; if (w >= HHs) w -= HHs;
        float4 v4 = *(const float4*)(g_qkv + (size_t)(b * HWp + h * HHs + w) * 288 + 96 * H + 4 * j);
        float vals[4] = {v4.x, v4.y, v4.z, v4.w};
#pragma unroll
        for (int dd = 0; dd < 4; dd++) {
            int c = 4 * j + dd;
            int e = c / 3, s = c - 3 * e;
            if (s == 0)      Qt[e][qi] = vals[dd];
            else if (s == 1) Kt[e][qi] = vals[dd];
            else             Vs[qi * 36 + e] = vals[dd];
        }
    }
    __syncthreads();

    const bool mrow = (xw == 7);
    const bool mcol = (yw == 7);

    // scores: 13x13 groups of 4x4 tiles (169 threads), covers 52x52
    if (tid < 169) {
        int ti = tid % 13, tj = tid / 13;
        int q0 = ti * 4, k0 = tj * 4;
        ull acc[4][2];
#pragma unroll
        for (int i = 0; i < 4; i++) { acc[i][0] = 0ULL; acc[i][1] = 0ULL; }
#pragma unroll 4
        for (int e = 0; e < EHh; e++) {
            float4 qv = *(const float4*)&Qt[e][q0];
            ulonglong2 kp = *(const ulonglong2*)&Kt[e][k0];
            float qa[4] = {qv.x, qv.y, qv.z, qv.w};
#pragma unroll
            for (int i = 0; i < 4; i++) {
                ull qd;
                DUP2(qd, qa[i]);
                FMA2(acc[i][0], qd, kp.x);
                FMA2(acc[i][1], qd, kp.y);
            }
        }
#pragma unroll
        for (int i = 0; i < 4; i++) {
            int qi = q0 + i;
            bool qr = (qi / WSw >= 4);
            bool qc = (qi % WSw >= 4);
#pragma unroll
            for (int jp = 0; jp < 2; jp++) {
                float lo, hi;
                UNPK(lo, hi, acc[i][jp]);
                float sv[2] = {lo, hi};
#pragma unroll
                for (int dd = 0; dd < 2; dd++) {
                    int ki = k0 + 2 * jp + dd;
                    float s = sv[dd] * 0.17677669529663687f;   // 1/sqrt(32)
                    if (mrow && ((ki / WSw >= 4) != qr)) s = -1e30f;
                    if (mcol && ((ki % WSw >= 4) != qc)) s = -1e30f;
                    S[qi][ki] = s;
                }
            }
        }
    }
    __syncthreads();

    // softmax: one warp per row (rows 0..48)
    {
        int wid = tid / 32, lane = tid % 32;
        for (int r = wid; r < WWq; r += 8) {
            float v1 = (lane < WWq)      ? S[r][lane]      : -1e30f;
            float v2 = (lane + 32 < WWq) ? S[r][lane + 32] : -1e30f;
            float mx = fmaxf(v1, v2);
#pragma unroll
            for (int o = 16; o; o >>= 1) mx = fmaxf(mx, __shfl_xor_sync(0xffffffffu, mx, o));
            float e1 = (lane < WWq)      ? __expf(v1 - mx) : 0.f;
            float e2 = (lane + 32 < WWq) ? __expf(v2 - mx) : 0.f;
            float sm = e1 + e2;
#pragma unroll
            for (int o = 16; o; o >>= 1) sm += __shfl_xor_sync(0xffffffffu, sm, o);
            float inv = __frcp_rn(sm);
            if (lane < WWq)      S[r][lane]      = e1 * inv;
            if (lane + 32 < WWq) S[r][lane + 32] = e2 * inv;
        }
    }
    __syncthreads();

    // PV: 25 qi-groups (of 2) x 8 eh-groups (of 4) = 200 threads
    if (tid < 200) {
        int ti = tid % 25, tj = tid / 25;
        int q0 = ti * 2, e0 = tj * 4;
        ull acc[2][2];
        acc[0][0] = acc[0][1] = acc[1][0] = acc[1][1] = 0ULL;
#pragma unroll 7
        for (int kk = 0; kk < WWq; kk++) {
            ulonglong2 vp = *(const ulonglong2*)&Vs[kk * 36 + e0];
            ull pd0, pd1;
            DUP2(pd0, S[q0][kk]);
            DUP2(pd1, S[q0 + 1][kk]);
            FMA2(acc[0][0], pd0, vp.x);
            FMA2(acc[0][1], pd0, vp.y);
            FMA2(acc[1][0], pd1, vp.x);
            FMA2(acc[1][1], pd1, vp.y);
        }
#pragma unroll
        for (int i = 0; i < 2; i++) {
            int qi = q0 + i;
            if (qi < WWq) {
                int m1 = qi / WSw, m2 = qi % WSw;
                int h = (xw * WSw + m1 + 3) % HHs;   // roll +3 (faithful)
                int w = (yw * WSw + m2 + 3) % HHs;
                float* dst = g_o + ((size_t)b * HWp + h * HHs + w) * EE + H * EHh + e0;
                float l0, h0, l1, h1;
                UNPK(l0, h0, acc[i][0]);
                UNPK(l1, h1, acc[i][1]);
                *(float4*)dst = make_float4(l0, h0, l1, h1);
            }
        }
    }
}

// ---------------------------------------------------------------------------
extern "C" void kernel_launch(void* const* d_in, const int* in_sizes, int n_in,
                              void* d_out, int out_size) {
    const float* x  = (const float*)d_in[0];
    const float* w1 = (const float*)d_in[1];
    const float* b1 = (const float*)d_in[2];
    const float* w2 = (const float*)d_in[3];
    const float* b2 = (const float*)d_in[4];
    float* out = (float*)d_out;

    cudaFuncSetAttribute(qkv_mma, cudaFuncAttributeMaxDynamicSharedMemorySize, SM_SZ);
    cudaFuncSetAttribute(proj_mma, cudaFuncAttributeMaxDynamicSharedMemorySize, SM_SZ);

    wconv_kernel<<<64, 256>>>(w1, w2);
    qkv_mma<<<BB * HWp / 128, 256, SM_SZ>>>(x, b1);
    attn_kernel<<<BB * NHh * NWIN, 256>>>();
    proj_mma<<<BB * HWp / 128, 256, SM_SZ>>>(b2, out);
}